// round 3
// baseline (speedup 1.0000x reference)
#include <cuda_runtime.h>

// CPPN: [P,12] -> 32 -> 32 -> 32 -> 3, per-node activations, tanh output.
// Strategy: compute-bound on FP32 pipe -> use packed f32x2 FFMA (FFMA2).
// Pack PAIRS OF OUTPUT NODES per f32x2 so the weight pair comes directly from
// an LDS.128 of the row-major weight matrix (4 output weights / load).
// Hidden state lives in registers as duplicated f32x2; weights in shared.

typedef unsigned long long ull;

__device__ __forceinline__ ull pk2(float lo, float hi) {
    ull r; asm("mov.b64 %0, {%1, %2};" : "=l"(r) : "f"(lo), "f"(hi)); return r;
}
__device__ __forceinline__ ull dup2(float x) { return pk2(x, x); }
__device__ __forceinline__ ull ffma2(ull a, ull b, ull c) {
    ull d; asm("fma.rn.f32x2 %0, %1, %2, %3;" : "=l"(d) : "l"(a), "l"(b), "l"(c)); return d;
}
__device__ __forceinline__ void unpk2(ull v, float& lo, float& hi) {
    asm("mov.b64 {%0, %1}, %2;" : "=f"(lo), "=f"(hi) : "l"(v));
}

// Overflow-safe fast tanh: tanh(x) = sign(x) * (1-e)/(1+e), e = exp(-2|x|) <= 1
__device__ __forceinline__ float fast_tanh(float x) {
    float ax = fabsf(x);
    float e  = __expf(-2.0f * ax);
    float t  = __fdividef(1.0f - e, 1.0f + e);
    return copysignf(t, x);
}

// 0=identity, 1=tanh, 2=sigmoid, 3=sin, 4=gaussian
__device__ __forceinline__ float actf(float x, int id) {
    switch (id) {
        case 1:  return fast_tanh(x);
        case 2:  return __fdividef(1.0f, 1.0f + __expf(-x));
        case 3:  return __sinf(x);
        case 4:  return __expf(-0.5f * x * x);
        default: return x;
    }
}

// One hidden layer: K inputs (duplicated f32x2), 32 outputs (written duplicated).
// sW row-major [K][32]; output pairs come from LDS.128 quads.
template <int K>
__device__ __forceinline__ void layerf(const ull* __restrict__ hp, ull* __restrict__ ho,
                                       const float* __restrict__ sW,
                                       const float* __restrict__ sb,
                                       const int* __restrict__ sact) {
#pragma unroll
    for (int jq = 0; jq < 8; jq++) {
        ull a0 = pk2(sb[4 * jq + 0], sb[4 * jq + 1]);
        ull a1 = pk2(sb[4 * jq + 2], sb[4 * jq + 3]);
#pragma unroll
        for (int k = 0; k < K; k++) {
            float4 w = *(const float4*)(sW + k * 32 + 4 * jq);
            a0 = ffma2(hp[k], pk2(w.x, w.y), a0);
            a1 = ffma2(hp[k], pk2(w.z, w.w), a1);
        }
        float x0, x1, x2, x3;
        unpk2(a0, x0, x1);
        unpk2(a1, x2, x3);
        ho[4 * jq + 0] = dup2(actf(x0, sact[4 * jq + 0]));
        ho[4 * jq + 1] = dup2(actf(x1, sact[4 * jq + 1]));
        ho[4 * jq + 2] = dup2(actf(x2, sact[4 * jq + 2]));
        ho[4 * jq + 3] = dup2(actf(x3, sact[4 * jq + 3]));
    }
}

__global__ __launch_bounds__(128) void cppn_kernel(
    const float* __restrict__ inp,       // [P,12]
    const float* __restrict__ bias_in,   // [12]
    const float* __restrict__ W1,        // [12,32]
    const float* __restrict__ b1,        // [32]
    const int*   __restrict__ a1,        // [32]
    const float* __restrict__ W2,        // [32,32]
    const float* __restrict__ b2,
    const int*   __restrict__ a2,
    const float* __restrict__ W3,        // [32,32]
    const float* __restrict__ b3,
    const int*   __restrict__ a3,
    const float* __restrict__ Wo,        // [32,3]
    const float* __restrict__ bo,        // [3]
    float* __restrict__ out,             // [P,3]
    int P)
{
    __shared__ __align__(16) float sW1[12 * 32];
    __shared__ __align__(16) float sW2[32 * 32];
    __shared__ __align__(16) float sW3[32 * 32];
    __shared__ float sWo[96];
    __shared__ float sb1[32], sb2[32], sb3[32], sbo[3], sbin[12];
    __shared__ int   sa1[32], sa2[32], sa3[32];

    const int t = threadIdx.x;
    for (int i = t; i < 12 * 32; i += 128) sW1[i] = W1[i];
    for (int i = t; i < 1024; i += 128) { sW2[i] = W2[i]; sW3[i] = W3[i]; }
    if (t < 96) sWo[t] = Wo[t];
    if (t < 32) {
        sb1[t] = b1[t]; sb2[t] = b2[t]; sb3[t] = b3[t];
        sa1[t] = a1[t]; sa2[t] = a2[t]; sa3[t] = a3[t];
    }
    if (t < 12) sbin[t] = bias_in[t];
    if (t < 3)  sbo[t]  = bo[t];
    __syncthreads();

    const int p = blockIdx.x * 128 + t;
    if (p >= P) return;

    // Load 12 inputs as 3x float4 (rows are 48B, 16B-aligned)
    const float4* in4 = (const float4*)inp;
    float4 A = in4[3 * p + 0];
    float4 B = in4[3 * p + 1];
    float4 C = in4[3 * p + 2];

    ull ip[12];
    ip[0]  = dup2(A.x + sbin[0]);  ip[1]  = dup2(A.y + sbin[1]);
    ip[2]  = dup2(A.z + sbin[2]);  ip[3]  = dup2(A.w + sbin[3]);
    ip[4]  = dup2(B.x + sbin[4]);  ip[5]  = dup2(B.y + sbin[5]);
    ip[6]  = dup2(B.z + sbin[6]);  ip[7]  = dup2(B.w + sbin[7]);
    ip[8]  = dup2(C.x + sbin[8]);  ip[9]  = dup2(C.y + sbin[9]);
    ip[10] = dup2(C.z + sbin[10]); ip[11] = dup2(C.w + sbin[11]);

    ull hA[32], hB[32];
    layerf<12>(ip, hA, sW1, sb1, sa1);
    layerf<32>(hA, hB, sW2, sb2, sa2);
    layerf<32>(hB, hA, sW3, sb3, sa3);

    // Output layer: 32 -> 3, then tanh
    float o0 = sbo[0], o1 = sbo[1], o2 = sbo[2];
#pragma unroll
    for (int k = 0; k < 32; k++) {
        float hk, dummy;
        unpk2(hA[k], hk, dummy);
        o0 = fmaf(hk, sWo[3 * k + 0], o0);
        o1 = fmaf(hk, sWo[3 * k + 1], o1);
        o2 = fmaf(hk, sWo[3 * k + 2], o2);
    }
    out[3 * p + 0] = fast_tanh(o0);
    out[3 * p + 1] = fast_tanh(o1);
    out[3 * p + 2] = fast_tanh(o2);
}

extern "C" void kernel_launch(void* const* d_in, const int* in_sizes, int n_in,
                              void* d_out, int out_size) {
    const float* inp  = (const float*)d_in[0];
    const float* bin  = (const float*)d_in[1];
    const float* W1   = (const float*)d_in[2];
    const float* b1   = (const float*)d_in[3];
    const int*   a1   = (const int*)  d_in[4];
    const float* W2   = (const float*)d_in[5];
    const float* b2   = (const float*)d_in[6];
    const int*   a2   = (const int*)  d_in[7];
    const float* W3   = (const float*)d_in[8];
    const float* b3   = (const float*)d_in[9];
    const int*   a3   = (const int*)  d_in[10];
    const float* Wo   = (const float*)d_in[11];
    const float* bo   = (const float*)d_in[12];
    float* out = (float*)d_out;

    const int P = in_sizes[0] / 12;
    const int blocks = (P + 127) / 128;
    cppn_kernel<<<blocks, 128>>>(inp, bin, W1, b1, a1, W2, b2, a2,
                                 W3, b3, a3, Wo, bo, out, P);
}